// round 12
// baseline (speedup 1.0000x reference)
#include <cuda_runtime.h>
#include <mma.h>
#include <cstdint>

using namespace nvcuda;

// ---------------- problem constants ----------------
#define D_MODEL 1024
#define HEADS   16
#define DH      64
#define HIDDEN  4096
#define BATCH   4
#define SEQ     2048
#define DIL     2
#define GRP     (BATCH*DIL)      // 8
#define LSEQ    (SEQ/DIL)        // 1024 (pad = 0 since S % d == 0)
#define MROWS   (BATCH*SEQ)      // 8192
#define LN_EPS  1e-5f

// ---------------- scratch (static device globals; no runtime alloc) ----------
__device__ float g_xg  [MROWS * D_MODEL];
__device__ float g_q   [GRP * HEADS * LSEQ * DH];
__device__ float g_k   [GRP * HEADS * LSEQ * DH];
__device__ float g_v   [GRP * HEADS * LSEQ * DH];
__device__ float g_attn[MROWS * D_MODEL];
__device__ float g_tmp1[MROWS * D_MODEL];
__device__ float g_fin [MROWS * D_MODEL];
__device__ float g_hid [MROWS * HIDDEN];
__device__ float g_tmp2[MROWS * D_MODEL];

// ---------------- gather: x(B,S,D) -> xg(G,L,D) -----------------------------
__global__ void __launch_bounds__(256) gather_kernel(const float* __restrict__ x) {
    int m = blockIdx.x;                 // g*L + l
    int g = m >> 10, l = m & 1023;
    int b = g >> 1,  j = g & 1;
    int s = l * DIL + j;
    const float4* src = (const float4*)(x + ((size_t)b * SEQ + s) * D_MODEL);
    float4* dst = (float4*)(g_xg + (size_t)m * D_MODEL);
    dst[threadIdx.x] = src[threadIdx.x];
}

// ---------------- TF32 WMMA GEMM: 64x64 tile, BK=16, 256 threads -------------
// MODE 0: C[m,n] = acc + bias[n]
// MODE 1: C[m,n] = relu(acc + bias[n])
// MODE 2: QKV scatter to [(g*HEADS+h)*L + l]*DH + dd  (BN=64 => one head/block)
#define GBM 64
#define GBN 64
#define GBK 16
#define A_LD 24    // 64 x 24 floats
#define B_LD 72    // 16 x 72 floats
#define C_LD 68    // 64 x 68 floats

template<int MODE>
__global__ void __launch_bounds__(256) wmma_gemm_kernel(
    const float* __restrict__ A, const float* __restrict__ Bm,
    const float* __restrict__ bias, float* __restrict__ C,
    int M, int N, int K)
{
    // union: As+Bs (2688 floats) overlapped with Cs (4352 floats)
    __shared__ float sbuf[GBM * C_LD];
    float (*As)[A_LD] = (float(*)[A_LD])sbuf;
    float (*Bs)[B_LD] = (float(*)[B_LD])(sbuf + GBM * A_LD);
    float (*Cs)[C_LD] = (float(*)[C_LD])sbuf;

    const int tid = threadIdx.x;
    const int wid = tid >> 5;
    const int bm = blockIdx.y * GBM;
    const int bn = blockIdx.x * GBN;

    // warp tile: rows rt*16, cols cg*32 (2 x 16x16 accum tiles)
    const int rt = wid & 3;
    const int cg = wid >> 2;

    // A load mapping: thread -> (row = tid/4, col4 = tid%4)
    const int a_row = tid >> 2, a_c4 = (tid & 3) * 4;
    // B load mapping: thread -> (row = tid/16, col4 = tid%16)
    const int b_row = tid >> 4, b_c4 = (tid & 15) * 4;

    const float* Aptr = A + (size_t)(bm + a_row) * K + a_c4;
    const float* Bptr = Bm + (size_t)b_row * N + bn + b_c4;

    wmma::fragment<wmma::accumulator, 16, 16, 8, float> acc[2];
    wmma::fill_fragment(acc[0], 0.0f);
    wmma::fill_fragment(acc[1], 0.0f);

    for (int k0 = 0; k0 < K; k0 += GBK) {
        *(float4*)&As[a_row][a_c4] = *(const float4*)(Aptr + k0);
        *(float4*)&Bs[b_row][b_c4] = *(const float4*)(Bptr + (size_t)k0 * N);
        __syncthreads();

        #pragma unroll
        for (int kk = 0; kk < GBK; kk += 8) {
            wmma::fragment<wmma::matrix_a, 16, 16, 8, wmma::precision::tf32, wmma::row_major> a_frag;
            wmma::load_matrix_sync(a_frag, &As[rt * 16][kk], A_LD);
            #pragma unroll
            for (int t = 0; t < a_frag.num_elements; t++)
                a_frag.x[t] = wmma::__float_to_tf32(a_frag.x[t]);

            #pragma unroll
            for (int j = 0; j < 2; j++) {
                wmma::fragment<wmma::matrix_b, 16, 16, 8, wmma::precision::tf32, wmma::row_major> b_frag;
                wmma::load_matrix_sync(b_frag, &Bs[kk][cg * 32 + j * 16], B_LD);
                #pragma unroll
                for (int t = 0; t < b_frag.num_elements; t++)
                    b_frag.x[t] = wmma::__float_to_tf32(b_frag.x[t]);
                wmma::mma_sync(acc[j], a_frag, b_frag, acc[j]);
            }
        }
        __syncthreads();
    }

    // stage accumulators through shared, then epilogue
    wmma::store_matrix_sync(&Cs[rt * 16][cg * 32 +  0], acc[0], C_LD, wmma::mem_row_major);
    wmma::store_matrix_sync(&Cs[rt * 16][cg * 32 + 16], acc[1], C_LD, wmma::mem_row_major);
    __syncthreads();

    // 64x64 tile = 1024 float4; 256 threads x 4 iters
    #pragma unroll
    for (int it = 0; it < 4; it++) {
        int idx = tid + it * 256;       // 0..1023
        int r  = idx >> 4;              // 0..63
        int c4 = (idx & 15) * 4;        // 0..60
        float4 v = *(float4*)&Cs[r][c4];
        float4 bvv = *(const float4*)(bias + bn + c4);
        v.x += bvv.x; v.y += bvv.y; v.z += bvv.z; v.w += bvv.w;
        if (MODE == 1) {
            v.x = fmaxf(v.x, 0.f); v.y = fmaxf(v.y, 0.f);
            v.z = fmaxf(v.z, 0.f); v.w = fmaxf(v.w, 0.f);
        }
        int m = bm + r;
        if (MODE == 2) {
            // whole block is one head: h = bn>>6, dd = col
            int g = m >> 10, l = m & 1023;
            int h = bn >> 6;
            float* dst = C + (((size_t)(g * HEADS + h)) * LSEQ + l) * DH + c4;
            *(float4*)dst = v;
        } else {
            *(float4*)(C + (size_t)m * N + bn + c4) = v;
        }
    }
}

// ---------------- attention: flash-style, 32 q rows / CTA --------------------
__global__ void __launch_bounds__(256) attn_kernel(float* __restrict__ out_attn) {
    __shared__ float Qs[32][DH];
    __shared__ float KV[64][DH + 4];
    __shared__ float Ps[32][64];

    const int tid = threadIdx.x;
    const int gh  = blockIdx.y;
    const int g   = gh >> 4, h = gh & 15;
    const int q0  = blockIdx.x * 32;

    const float* Qg = g_q + (size_t)gh * LSEQ * DH;
    const float* Kg = g_k + (size_t)gh * LSEQ * DH;
    const float* Vg = g_v + (size_t)gh * LSEQ * DH;

    for (int i = tid; i < 32 * 16; i += 256) {
        int r = i >> 4, c = i & 15;
        ((float4*)&Qs[r][0])[c] = ((const float4*)&Qg[(size_t)(q0 + r) * DH])[c];
    }

    const int q   = tid >> 3;
    const int kc0 = tid & 7;
    const float scale = 0.125f;

    float m_run = -1e30f, l_run = 0.f;
    float O[8];
    #pragma unroll
    for (int c = 0; c < 8; c++) O[c] = 0.f;

    for (int kt = 0; kt < LSEQ / 64; kt++) {
        __syncthreads();
        for (int i = tid; i < 64 * 64; i += 256) {
            int kk = i >> 6, d = i & 63;
            KV[d][kk] = Kg[(size_t)(kt * 64 + kk) * DH + d];
        }
        __syncthreads();

        float s[8];
        #pragma unroll
        for (int c = 0; c < 8; c++) {
            int kc = kc0 + c * 8;
            float a0 = 0.f;
            #pragma unroll
            for (int d = 0; d < 64; d++) a0 += Qs[q][d] * KV[d][kc];
            s[c] = a0 * scale;
        }

        float mloc = s[0];
        #pragma unroll
        for (int c = 1; c < 8; c++) mloc = fmaxf(mloc, s[c]);
        #pragma unroll
        for (int off = 4; off; off >>= 1)
            mloc = fmaxf(mloc, __shfl_xor_sync(0xffffffffu, mloc, off, 8));
        float m_new = fmaxf(m_run, mloc);
        float corr  = __expf(m_run - m_new);

        float psum = 0.f;
        #pragma unroll
        for (int c = 0; c < 8; c++) { s[c] = __expf(s[c] - m_new); psum += s[c]; }
        #pragma unroll
        for (int off = 4; off; off >>= 1)
            psum += __shfl_xor_sync(0xffffffffu, psum, off, 8);

        l_run = l_run * corr + psum;
        m_run = m_new;
        #pragma unroll
        for (int c = 0; c < 8; c++) O[c] *= corr;

        #pragma unroll
        for (int c = 0; c < 8; c++) Ps[q][kc0 + c * 8] = s[c];
        __syncthreads();

        for (int i = tid; i < 64 * 64; i += 256) {
            int kk = i >> 6, d = i & 63;
            KV[kk][d] = Vg[(size_t)(kt * 64 + kk) * DH + d];
        }
        __syncthreads();

        #pragma unroll 8
        for (int k = 0; k < 64; k++) {
            float p = Ps[q][k];
            #pragma unroll
            for (int c = 0; c < 8; c++)
                O[c] += p * KV[k][kc0 + c * 8];
        }
    }

    float inv = 1.f / l_run;
    int b = g >> 1, j = g & 1;
    int srow = (q0 + q) * DIL + j;
    float* outp = out_attn + ((size_t)b * SEQ + srow) * D_MODEL + h * DH;
    #pragma unroll
    for (int c = 0; c < 8; c++) outp[kc0 + c * 8] = O[c] * inv;
}

// ---------------- residual + layernorm: out = LN(a + r) ---------------------
__global__ void __launch_bounds__(256) ln_kernel(
    const float* __restrict__ a, const float* __restrict__ r,
    const float* __restrict__ gamma, const float* __restrict__ beta,
    float* __restrict__ out)
{
    __shared__ float s_sum[8], s_sq[8];
    __shared__ float s_mu, s_rstd;
    const int row = blockIdx.x, tid = threadIdx.x;
    const size_t base = (size_t)row * D_MODEL;

    float4 av = ((const float4*)(a + base))[tid];
    float4 rv = ((const float4*)(r + base))[tid];
    float v0 = av.x + rv.x, v1 = av.y + rv.y, v2 = av.z + rv.z, v3 = av.w + rv.w;

    float sum = v0 + v1 + v2 + v3;
    float sq  = v0*v0 + v1*v1 + v2*v2 + v3*v3;
    #pragma unroll
    for (int off = 16; off; off >>= 1) {
        sum += __shfl_xor_sync(0xffffffffu, sum, off);
        sq  += __shfl_xor_sync(0xffffffffu, sq,  off);
    }
    if ((tid & 31) == 0) { s_sum[tid >> 5] = sum; s_sq[tid >> 5] = sq; }
    __syncthreads();
    if (tid == 0) {
        float ts = 0.f, tq = 0.f;
        #pragma unroll
        for (int i = 0; i < 8; i++) { ts += s_sum[i]; tq += s_sq[i]; }
        float mu  = ts * (1.f / D_MODEL);
        float var = tq * (1.f / D_MODEL) - mu * mu;
        s_mu = mu;
        s_rstd = rsqrtf(var + LN_EPS);
    }
    __syncthreads();
    float mu = s_mu, rstd = s_rstd;

    float4 gv = ((const float4*)gamma)[tid];
    float4 bv = ((const float4*)beta)[tid];
    float4 o;
    o.x = (v0 - mu) * rstd * gv.x + bv.x;
    o.y = (v1 - mu) * rstd * gv.y + bv.y;
    o.z = (v2 - mu) * rstd * gv.z + bv.z;
    o.w = (v3 - mu) * rstd * gv.w + bv.w;
    ((float4*)(out + base))[tid] = o;
}

// ---------------- launch ------------------------------------------------------
extern "C" void kernel_launch(void* const* d_in, const int* in_sizes, int n_in,
                              void* d_out, int out_size) {
    const float* x     = (const float*)d_in[0];
    const float* Wq    = (const float*)d_in[1];
    const float* bq    = (const float*)d_in[2];
    const float* Wk    = (const float*)d_in[3];
    const float* bk    = (const float*)d_in[4];
    const float* Wv    = (const float*)d_in[5];
    const float* bv    = (const float*)d_in[6];
    const float* Wo    = (const float*)d_in[7];
    const float* bo    = (const float*)d_in[8];
    const float* ln1_g = (const float*)d_in[9];
    const float* ln1_b = (const float*)d_in[10];
    const float* W1    = (const float*)d_in[11];
    const float* b1    = (const float*)d_in[12];
    const float* W2    = (const float*)d_in[13];
    const float* b2    = (const float*)d_in[14];
    const float* ln2_g = (const float*)d_in[15];
    const float* ln2_b = (const float*)d_in[16];
    float* out = (float*)d_out;

    float *p_xg, *p_q, *p_k, *p_v, *p_attn, *p_tmp1, *p_fin, *p_hid, *p_tmp2;
    cudaGetSymbolAddress((void**)&p_xg,   g_xg);
    cudaGetSymbolAddress((void**)&p_q,    g_q);
    cudaGetSymbolAddress((void**)&p_k,    g_k);
    cudaGetSymbolAddress((void**)&p_v,    g_v);
    cudaGetSymbolAddress((void**)&p_attn, g_attn);
    cudaGetSymbolAddress((void**)&p_tmp1, g_tmp1);
    cudaGetSymbolAddress((void**)&p_fin,  g_fin);
    cudaGetSymbolAddress((void**)&p_hid,  g_hid);
    cudaGetSymbolAddress((void**)&p_tmp2, g_tmp2);

    // 1. gather into dilated layout
    gather_kernel<<<MROWS, 256>>>(x);

    // 2. QKV projections (scatter into [g,h,l,dh])
    dim3 gD(D_MODEL / GBN, MROWS / GBM);      // (16, 128)
    wmma_gemm_kernel<2><<<gD, 256>>>(p_xg, Wq, bq, p_q, MROWS, D_MODEL, D_MODEL);
    wmma_gemm_kernel<2><<<gD, 256>>>(p_xg, Wk, bk, p_k, MROWS, D_MODEL, D_MODEL);
    wmma_gemm_kernel<2><<<gD, 256>>>(p_xg, Wv, bv, p_v, MROWS, D_MODEL, D_MODEL);

    // 3. attention -> ctx in (B,S,D)
    dim3 gAtt(LSEQ / 32, GRP * HEADS);
    attn_kernel<<<gAtt, 256>>>(p_attn);

    // 4. output projection
    wmma_gemm_kernel<0><<<gD, 256>>>(p_attn, Wo, bo, p_tmp1, MROWS, D_MODEL, D_MODEL);

    // 5. LN1
    ln_kernel<<<MROWS, 256>>>(p_tmp1, x, ln1_g, ln1_b, p_fin);

    // 6. FFN up + relu
    dim3 gH(HIDDEN / GBN, MROWS / GBM);       // (64, 128)
    wmma_gemm_kernel<1><<<gH, 256>>>(p_fin, W1, b1, p_hid, MROWS, HIDDEN, D_MODEL);

    // 7. FFN down
    wmma_gemm_kernel<0><<<gD, 256>>>(p_hid, W2, b2, p_tmp2, MROWS, D_MODEL, HIDDEN);

    // 8. LN2
    ln_kernel<<<MROWS, 256>>>(p_tmp2, p_fin, ln2_g, ln2_b, out);
}

// round 13
// speedup vs baseline: 1.1730x; 1.1730x over previous
#include <cuda_runtime.h>
#include <mma.h>
#include <cstdint>

using namespace nvcuda;

// ---------------- problem constants ----------------
#define D_MODEL 1024
#define HEADS   16
#define DH      64
#define HIDDEN  4096
#define BATCH   4
#define SEQ     2048
#define DIL     2
#define GRP     (BATCH*DIL)      // 8
#define LSEQ    (SEQ/DIL)        // 1024 (pad = 0 since S % d == 0)
#define MROWS   (BATCH*SEQ)      // 8192
#define LN_EPS  1e-5f

// ---------------- scratch (static device globals; no runtime alloc) ----------
__device__ float g_xg  [MROWS * D_MODEL];
__device__ float g_q   [GRP * HEADS * LSEQ * DH];
__device__ float g_k   [GRP * HEADS * LSEQ * DH];
__device__ float g_v   [GRP * HEADS * LSEQ * DH];
__device__ float g_attn[MROWS * D_MODEL];
__device__ float g_tmp1[MROWS * D_MODEL];
__device__ float g_fin [MROWS * D_MODEL];
__device__ float g_hid [MROWS * HIDDEN];
__device__ float g_tmp2[MROWS * D_MODEL];

// ---------------- gather: x(B,S,D) -> xg(G,L,D) -----------------------------
__global__ void __launch_bounds__(256) gather_kernel(const float* __restrict__ x) {
    int m = blockIdx.x;                 // g*L + l
    int g = m >> 10, l = m & 1023;
    int b = g >> 1,  j = g & 1;
    int s = l * DIL + j;
    const float4* src = (const float4*)(x + ((size_t)b * SEQ + s) * D_MODEL);
    float4* dst = (float4*)(g_xg + (size_t)m * D_MODEL);
    dst[threadIdx.x] = src[threadIdx.x];
}

// ---------------- TF32 WMMA GEMM: 128x128 tile, BK=16, 256 threads ----------
// 8 warps as 4 (row) x 2 (col); warp tile = 32x64 = 2x4 16x16 fragments.
// TF32 conversion hoisted to smem store; register-prefetch pipeline.
// MODE 0: C[m,n] = acc + bias[n]
// MODE 1: relu;  MODE 2: QKV scatter (warp col-block 64-wide = head-aligned)
#define BM 128
#define BN 128
#define BKK 16
#define A_LD 24      // 128 x 24 floats
#define B_LD 136     // 16 x 136 floats
#define W_LD 20      // per-warp epilogue staging 16 x 20

template<int MODE>
__global__ void __launch_bounds__(256) wmma_gemm_kernel(
    const float* __restrict__ A, const float* __restrict__ Bm,
    const float* __restrict__ bias, float* __restrict__ C,
    int M, int N, int K)
{
    __shared__ float As[BM][A_LD];        // 12.0 KB
    __shared__ float Bs[BKK][B_LD];       //  8.5 KB
    __shared__ float Ws[8][16][W_LD];     // 10.0 KB

    const int tid  = threadIdx.x;
    const int wid  = tid >> 5;
    const int lane = tid & 31;
    const int bm = blockIdx.y * BM;
    const int bn = blockIdx.x * BN;

    const int rt = wid & 3;      // warp row group: rows rt*32 .. rt*32+31
    const int cg = wid >> 1 >> 1; // wid>>2: warp col group: cols cg*64 .. cg*64+63

    // A tile 128x16: 512 float4, 256 thr x 2 (rows r and r+64)
    const int a_row = tid >> 2;            // 0..63
    const int a_c4  = (tid & 3) * 4;       // 0,4,8,12
    // B tile 16x128: 512 float4, 256 thr x 2 (cols c and c+64)
    const int b_row = tid >> 4;            // 0..15
    const int b_c4  = (tid & 15) * 4;      // 0..60

    const float* Aptr0 = A + (size_t)(bm + a_row) * K + a_c4;
    const float* Aptr1 = A + (size_t)(bm + a_row + 64) * K + a_c4;
    const float* Bptr0 = Bm + (size_t)b_row * N + bn + b_c4;
    const float* Bptr1 = Bm + (size_t)b_row * N + bn + b_c4 + 64;

    wmma::fragment<wmma::accumulator, 16, 16, 8, float> acc[2][4];
    #pragma unroll
    for (int i = 0; i < 2; i++)
        #pragma unroll
        for (int j = 0; j < 4; j++) wmma::fill_fragment(acc[i][j], 0.0f);

    // prefetch first tile
    float4 av0 = *(const float4*)(Aptr0);
    float4 av1 = *(const float4*)(Aptr1);
    float4 bv0 = *(const float4*)(Bptr0);
    float4 bv1 = *(const float4*)(Bptr1);

    for (int k0 = 0; k0 < K; k0 += BKK) {
        // store current tile (convert to TF32 once, here)
        As[a_row][a_c4 + 0]      = wmma::__float_to_tf32(av0.x);
        As[a_row][a_c4 + 1]      = wmma::__float_to_tf32(av0.y);
        As[a_row][a_c4 + 2]      = wmma::__float_to_tf32(av0.z);
        As[a_row][a_c4 + 3]      = wmma::__float_to_tf32(av0.w);
        As[a_row + 64][a_c4 + 0] = wmma::__float_to_tf32(av1.x);
        As[a_row + 64][a_c4 + 1] = wmma::__float_to_tf32(av1.y);
        As[a_row + 64][a_c4 + 2] = wmma::__float_to_tf32(av1.z);
        As[a_row + 64][a_c4 + 3] = wmma::__float_to_tf32(av1.w);
        Bs[b_row][b_c4 + 0]      = wmma::__float_to_tf32(bv0.x);
        Bs[b_row][b_c4 + 1]      = wmma::__float_to_tf32(bv0.y);
        Bs[b_row][b_c4 + 2]      = wmma::__float_to_tf32(bv0.z);
        Bs[b_row][b_c4 + 3]      = wmma::__float_to_tf32(bv0.w);
        Bs[b_row][b_c4 + 64]     = wmma::__float_to_tf32(bv1.x);
        Bs[b_row][b_c4 + 65]     = wmma::__float_to_tf32(bv1.y);
        Bs[b_row][b_c4 + 66]     = wmma::__float_to_tf32(bv1.z);
        Bs[b_row][b_c4 + 67]     = wmma::__float_to_tf32(bv1.w);
        __syncthreads();

        // issue next tile's loads before compute (latency overlap)
        int kn = k0 + BKK;
        if (kn < K) {
            av0 = *(const float4*)(Aptr0 + kn);
            av1 = *(const float4*)(Aptr1 + kn);
            bv0 = *(const float4*)(Bptr0 + (size_t)kn * N);
            bv1 = *(const float4*)(Bptr1 + (size_t)kn * N);
        }

        #pragma unroll
        for (int kk = 0; kk < BKK; kk += 8) {
            wmma::fragment<wmma::matrix_a, 16, 16, 8, wmma::precision::tf32, wmma::row_major> a_frag[2];
            wmma::load_matrix_sync(a_frag[0], &As[rt * 32][kk], A_LD);
            wmma::load_matrix_sync(a_frag[1], &As[rt * 32 + 16][kk], A_LD);
            #pragma unroll
            for (int j = 0; j < 4; j++) {
                wmma::fragment<wmma::matrix_b, 16, 16, 8, wmma::precision::tf32, wmma::row_major> b_frag;
                wmma::load_matrix_sync(b_frag, &Bs[kk][cg * 64 + j * 16], B_LD);
                wmma::mma_sync(acc[0][j], a_frag[0], b_frag, acc[0][j]);
                wmma::mma_sync(acc[1][j], a_frag[1], b_frag, acc[1][j]);
            }
        }
        __syncthreads();
    }

    // ---- per-warp epilogue: stage one 16x16 tile at a time ----
    const int h_head = (bn + cg * 64) >> 6;   // MODE 2: head index (64-aligned)
    #pragma unroll
    for (int i = 0; i < 2; i++) {
        #pragma unroll
        for (int j = 0; j < 4; j++) {
            wmma::store_matrix_sync(&Ws[wid][0][0], acc[i][j], W_LD, wmma::mem_row_major);
            __syncwarp();
            int row0 = bm + rt * 32 + i * 16;
            int col0 = bn + cg * 64 + j * 16;
            int r0 = lane >> 2;              // 0..7
            int c4 = (lane & 3) * 4;         // 0..12
            float4 bvv = *(const float4*)(bias + col0 + c4);
            #pragma unroll
            for (int rr = 0; rr < 2; rr++) {
                int r = r0 + rr * 8;
                float4 v = *(float4*)&Ws[wid][r][c4];
                v.x += bvv.x; v.y += bvv.y; v.z += bvv.z; v.w += bvv.w;
                if (MODE == 1) {
                    v.x = fmaxf(v.x, 0.f); v.y = fmaxf(v.y, 0.f);
                    v.z = fmaxf(v.z, 0.f); v.w = fmaxf(v.w, 0.f);
                }
                int m = row0 + r;
                if (MODE == 2) {
                    int g = m >> 10, l = m & 1023;
                    int dd = j * 16 + c4;    // (col0 & 63) + c4
                    float* dst = C + (((size_t)(g * HEADS + h_head)) * LSEQ + l) * DH + dd;
                    *(float4*)dst = v;
                } else {
                    *(float4*)(C + (size_t)m * N + col0 + c4) = v;
                }
            }
            __syncwarp();
        }
    }
}

// ---------------- attention: flash-style, 32 q rows / CTA --------------------
__global__ void __launch_bounds__(256) attn_kernel(float* __restrict__ out_attn) {
    __shared__ float Qs[32][DH];
    __shared__ float KV[64][DH + 4];
    __shared__ float Ps[32][64];

    const int tid = threadIdx.x;
    const int gh  = blockIdx.y;
    const int g   = gh >> 4, h = gh & 15;
    const int q0  = blockIdx.x * 32;

    const float* Qg = g_q + (size_t)gh * LSEQ * DH;
    const float* Kg = g_k + (size_t)gh * LSEQ * DH;
    const float* Vg = g_v + (size_t)gh * LSEQ * DH;

    for (int i = tid; i < 32 * 16; i += 256) {
        int r = i >> 4, c = i & 15;
        ((float4*)&Qs[r][0])[c] = ((const float4*)&Qg[(size_t)(q0 + r) * DH])[c];
    }

    const int q   = tid >> 3;
    const int kc0 = tid & 7;
    const float scale = 0.125f;

    float m_run = -1e30f, l_run = 0.f;
    float O[8];
    #pragma unroll
    for (int c = 0; c < 8; c++) O[c] = 0.f;

    for (int kt = 0; kt < LSEQ / 64; kt++) {
        __syncthreads();
        for (int i = tid; i < 64 * 64; i += 256) {
            int kk = i >> 6, d = i & 63;
            KV[d][kk] = Kg[(size_t)(kt * 64 + kk) * DH + d];
        }
        __syncthreads();

        float s[8];
        #pragma unroll
        for (int c = 0; c < 8; c++) {
            int kc = kc0 + c * 8;
            float a0 = 0.f;
            #pragma unroll
            for (int d = 0; d < 64; d++) a0 += Qs[q][d] * KV[d][kc];
            s[c] = a0 * scale;
        }

        float mloc = s[0];
        #pragma unroll
        for (int c = 1; c < 8; c++) mloc = fmaxf(mloc, s[c]);
        #pragma unroll
        for (int off = 4; off; off >>= 1)
            mloc = fmaxf(mloc, __shfl_xor_sync(0xffffffffu, mloc, off, 8));
        float m_new = fmaxf(m_run, mloc);
        float corr  = __expf(m_run - m_new);

        float psum = 0.f;
        #pragma unroll
        for (int c = 0; c < 8; c++) { s[c] = __expf(s[c] - m_new); psum += s[c]; }
        #pragma unroll
        for (int off = 4; off; off >>= 1)
            psum += __shfl_xor_sync(0xffffffffu, psum, off, 8);

        l_run = l_run * corr + psum;
        m_run = m_new;
        #pragma unroll
        for (int c = 0; c < 8; c++) O[c] *= corr;

        #pragma unroll
        for (int c = 0; c < 8; c++) Ps[q][kc0 + c * 8] = s[c];
        __syncthreads();

        for (int i = tid; i < 64 * 64; i += 256) {
            int kk = i >> 6, d = i & 63;
            KV[kk][d] = Vg[(size_t)(kt * 64 + kk) * DH + d];
        }
        __syncthreads();

        #pragma unroll 8
        for (int k = 0; k < 64; k++) {
            float p = Ps[q][k];
            #pragma unroll
            for (int c = 0; c < 8; c++)
                O[c] += p * KV[k][kc0 + c * 8];
        }
    }

    float inv = 1.f / l_run;
    int b = g >> 1, j = g & 1;
    int srow = (q0 + q) * DIL + j;
    float* outp = out_attn + ((size_t)b * SEQ + srow) * D_MODEL + h * DH;
    #pragma unroll
    for (int c = 0; c < 8; c++) outp[kc0 + c * 8] = O[c] * inv;
}

// ---------------- residual + layernorm: out = LN(a + r) ---------------------
__global__ void __launch_bounds__(256) ln_kernel(
    const float* __restrict__ a, const float* __restrict__ r,
    const float* __restrict__ gamma, const float* __restrict__ beta,
    float* __restrict__ out)
{
    __shared__ float s_sum[8], s_sq[8];
    __shared__ float s_mu, s_rstd;
    const int row = blockIdx.x, tid = threadIdx.x;
    const size_t base = (size_t)row * D_MODEL;

    float4 av = ((const float4*)(a + base))[tid];
    float4 rv = ((const float4*)(r + base))[tid];
    float v0 = av.x + rv.x, v1 = av.y + rv.y, v2 = av.z + rv.z, v3 = av.w + rv.w;

    float sum = v0 + v1 + v2 + v3;
    float sq  = v0*v0 + v1*v1 + v2*v2 + v3*v3;
    #pragma unroll
    for (int off = 16; off; off >>= 1) {
        sum += __shfl_xor_sync(0xffffffffu, sum, off);
        sq  += __shfl_xor_sync(0xffffffffu, sq,  off);
    }
    if ((tid & 31) == 0) { s_sum[tid >> 5] = sum; s_sq[tid >> 5] = sq; }
    __syncthreads();
    if (tid == 0) {
        float ts = 0.f, tq = 0.f;
        #pragma unroll
        for (int i = 0; i < 8; i++) { ts += s_sum[i]; tq += s_sq[i]; }
        float mu  = ts * (1.f / D_MODEL);
        float var = tq * (1.f / D_MODEL) - mu * mu;
        s_mu = mu;
        s_rstd = rsqrtf(var + LN_EPS);
    }
    __syncthreads();
    float mu = s_mu, rstd = s_rstd;

    float4 gv = ((const float4*)gamma)[tid];
    float4 bv = ((const float4*)beta)[tid];
    float4 o;
    o.x = (v0 - mu) * rstd * gv.x + bv.x;
    o.y = (v1 - mu) * rstd * gv.y + bv.y;
    o.z = (v2 - mu) * rstd * gv.z + bv.z;
    o.w = (v3 - mu) * rstd * gv.w + bv.w;
    ((float4*)(out + base))[tid] = o;
}

// ---------------- launch ------------------------------------------------------
extern "C" void kernel_launch(void* const* d_in, const int* in_sizes, int n_in,
                              void* d_out, int out_size) {
    const float* x     = (const float*)d_in[0];
    const float* Wq    = (const float*)d_in[1];
    const float* bq    = (const float*)d_in[2];
    const float* Wk    = (const float*)d_in[3];
    const float* bk    = (const float*)d_in[4];
    const float* Wv    = (const float*)d_in[5];
    const float* bv    = (const float*)d_in[6];
    const float* Wo    = (const float*)d_in[7];
    const float* bo    = (const float*)d_in[8];
    const float* ln1_g = (const float*)d_in[9];
    const float* ln1_b = (const float*)d_in[10];
    const float* W1    = (const float*)d_in[11];
    const float* b1    = (const float*)d_in[12];
    const float* W2    = (const float*)d_in[13];
    const float* b2    = (const float*)d_in[14];
    const float* ln2_g = (const float*)d_in[15];
    const float* ln2_b = (const float*)d_in[16];
    float* out = (float*)d_out;

    float *p_xg, *p_q, *p_k, *p_v, *p_attn, *p_tmp1, *p_fin, *p_hid, *p_tmp2;
    cudaGetSymbolAddress((void**)&p_xg,   g_xg);
    cudaGetSymbolAddress((void**)&p_q,    g_q);
    cudaGetSymbolAddress((void**)&p_k,    g_k);
    cudaGetSymbolAddress((void**)&p_v,    g_v);
    cudaGetSymbolAddress((void**)&p_attn, g_attn);
    cudaGetSymbolAddress((void**)&p_tmp1, g_tmp1);
    cudaGetSymbolAddress((void**)&p_fin,  g_fin);
    cudaGetSymbolAddress((void**)&p_hid,  g_hid);
    cudaGetSymbolAddress((void**)&p_tmp2, g_tmp2);

    // 1. gather into dilated layout
    gather_kernel<<<MROWS, 256>>>(x);

    // 2. QKV projections (scatter into [g,h,l,dh])
    dim3 gD(D_MODEL / BN, MROWS / BM);        // (8, 64)
    wmma_gemm_kernel<2><<<gD, 256>>>(p_xg, Wq, bq, p_q, MROWS, D_MODEL, D_MODEL);
    wmma_gemm_kernel<2><<<gD, 256>>>(p_xg, Wk, bk, p_k, MROWS, D_MODEL, D_MODEL);
    wmma_gemm_kernel<2><<<gD, 256>>>(p_xg, Wv, bv, p_v, MROWS, D_MODEL, D_MODEL);

    // 3. attention -> ctx in (B,S,D)
    dim3 gAtt(LSEQ / 32, GRP * HEADS);
    attn_kernel<<<gAtt, 256>>>(p_attn);

    // 4. output projection
    wmma_gemm_kernel<0><<<gD, 256>>>(p_attn, Wo, bo, p_tmp1, MROWS, D_MODEL, D_MODEL);

    // 5. LN1
    ln_kernel<<<MROWS, 256>>>(p_tmp1, x, ln1_g, ln1_b, p_fin);

    // 6. FFN up + relu
    dim3 gH(HIDDEN / BN, MROWS / BM);         // (32, 64)
    wmma_gemm_kernel<1><<<gH, 256>>>(p_fin, W1, b1, p_hid, MROWS, HIDDEN, D_MODEL);

    // 7. FFN down
    wmma_gemm_kernel<0><<<gD, 256>>>(p_hid, W2, b2, p_tmp2, MROWS, D_MODEL, HIDDEN);

    // 8. LN2
    ln_kernel<<<MROWS, 256>>>(p_tmp2, p_fin, ln2_g, ln2_b, out);
}

// round 14
// speedup vs baseline: 1.3156x; 1.1216x over previous
#include <cuda_runtime.h>
#include <mma.h>
#include <cstdint>

using namespace nvcuda;

// ---------------- problem constants ----------------
#define D_MODEL 1024
#define HEADS   16
#define DH      64
#define HIDDEN  4096
#define BATCH   4
#define SEQ     2048
#define DIL     2
#define GRP     (BATCH*DIL)      // 8
#define LSEQ    (SEQ/DIL)        // 1024
#define MROWS   (BATCH*SEQ)      // 8192
#define LN_EPS  1e-5f

// ---------------- scratch ----------------------------------------------------
__device__ float g_xg  [MROWS * D_MODEL];
__device__ float g_q   [GRP * HEADS * LSEQ * DH];
__device__ float g_k   [GRP * HEADS * LSEQ * DH];
__device__ float g_v   [GRP * HEADS * LSEQ * DH];
__device__ float g_attn[MROWS * D_MODEL];
__device__ float g_tmp1[MROWS * D_MODEL];
__device__ float g_fin [MROWS * D_MODEL];
__device__ float g_hid [MROWS * HIDDEN];
__device__ float g_tmp2[MROWS * D_MODEL];

// ---------------- gather -----------------------------------------------------
__global__ void __launch_bounds__(256) gather_kernel(const float* __restrict__ x) {
    int m = blockIdx.x;
    int g = m >> 10, l = m & 1023;
    int b = g >> 1,  j = g & 1;
    int s = l * DIL + j;
    const float4* src = (const float4*)(x + ((size_t)b * SEQ + s) * D_MODEL);
    float4* dst = (float4*)(g_xg + (size_t)m * D_MODEL);
    dst[threadIdx.x] = src[threadIdx.x];
}

// ---------------- TF32 WMMA GEMM: 128x128, BK=16, double-buffered ------------
#define BM 128
#define BN 128
#define BKK 16
#define A_LD 24
#define B_LD 136
#define W_LD 20

template<int MODE>
__global__ void __launch_bounds__(256) wmma_gemm_kernel(
    const float* __restrict__ A, const float* __restrict__ Bm,
    const float* __restrict__ bias, float* __restrict__ C,
    int M, int N, int K)
{
    __shared__ float As[2][BM][A_LD];     // 24 KB (aliased as epilogue staging)
    __shared__ float Bs[2][BKK][B_LD];    // 17.4 KB

    const int tid  = threadIdx.x;
    const int wid  = tid >> 5;
    const int lane = tid & 31;
    const int bm = blockIdx.y * BM;
    const int bn = blockIdx.x * BN;

    const int rt = wid & 3;
    const int cg = wid >> 2;

    const int a_row = tid >> 2;
    const int a_c4  = (tid & 3) * 4;
    const int b_row = tid >> 4;
    const int b_c4  = (tid & 15) * 4;

    const float* Aptr0 = A + (size_t)(bm + a_row) * K + a_c4;
    const float* Aptr1 = A + (size_t)(bm + a_row + 64) * K + a_c4;
    const float* Bptr0 = Bm + (size_t)b_row * N + bn + b_c4;
    const float* Bptr1 = Bm + (size_t)b_row * N + bn + b_c4 + 64;

    wmma::fragment<wmma::accumulator, 16, 16, 8, float> acc[2][4];
    #pragma unroll
    for (int i = 0; i < 2; i++)
        #pragma unroll
        for (int j = 0; j < 4; j++) wmma::fill_fragment(acc[i][j], 0.0f);

    float4 av0 = *(const float4*)(Aptr0);
    float4 av1 = *(const float4*)(Aptr1);
    float4 bv0 = *(const float4*)(Bptr0);
    float4 bv1 = *(const float4*)(Bptr1);

    // fill buffer 0
    {
        As[0][a_row][a_c4+0]      = wmma::__float_to_tf32(av0.x);
        As[0][a_row][a_c4+1]      = wmma::__float_to_tf32(av0.y);
        As[0][a_row][a_c4+2]      = wmma::__float_to_tf32(av0.z);
        As[0][a_row][a_c4+3]      = wmma::__float_to_tf32(av0.w);
        As[0][a_row+64][a_c4+0]   = wmma::__float_to_tf32(av1.x);
        As[0][a_row+64][a_c4+1]   = wmma::__float_to_tf32(av1.y);
        As[0][a_row+64][a_c4+2]   = wmma::__float_to_tf32(av1.z);
        As[0][a_row+64][a_c4+3]   = wmma::__float_to_tf32(av1.w);
        Bs[0][b_row][b_c4+0]      = wmma::__float_to_tf32(bv0.x);
        Bs[0][b_row][b_c4+1]      = wmma::__float_to_tf32(bv0.y);
        Bs[0][b_row][b_c4+2]      = wmma::__float_to_tf32(bv0.z);
        Bs[0][b_row][b_c4+3]      = wmma::__float_to_tf32(bv0.w);
        Bs[0][b_row][b_c4+64]     = wmma::__float_to_tf32(bv1.x);
        Bs[0][b_row][b_c4+65]     = wmma::__float_to_tf32(bv1.y);
        Bs[0][b_row][b_c4+66]     = wmma::__float_to_tf32(bv1.z);
        Bs[0][b_row][b_c4+67]     = wmma::__float_to_tf32(bv1.w);
    }
    __syncthreads();

    int p = 0;
    for (int k0 = 0; k0 < K; k0 += BKK) {
        int kn = k0 + BKK;
        bool more = kn < K;
        if (more) {
            av0 = *(const float4*)(Aptr0 + kn);
            av1 = *(const float4*)(Aptr1 + kn);
            bv0 = *(const float4*)(Bptr0 + (size_t)kn * N);
            bv1 = *(const float4*)(Bptr1 + (size_t)kn * N);
        }

        #pragma unroll
        for (int kk = 0; kk < BKK; kk += 8) {
            wmma::fragment<wmma::matrix_a, 16, 16, 8, wmma::precision::tf32, wmma::row_major> a_frag[2];
            wmma::load_matrix_sync(a_frag[0], &As[p][rt * 32][kk], A_LD);
            wmma::load_matrix_sync(a_frag[1], &As[p][rt * 32 + 16][kk], A_LD);
            #pragma unroll
            for (int j = 0; j < 4; j++) {
                wmma::fragment<wmma::matrix_b, 16, 16, 8, wmma::precision::tf32, wmma::row_major> b_frag;
                wmma::load_matrix_sync(b_frag, &Bs[p][kk][cg * 64 + j * 16], B_LD);
                wmma::mma_sync(acc[0][j], a_frag[0], b_frag, acc[0][j]);
                wmma::mma_sync(acc[1][j], a_frag[1], b_frag, acc[1][j]);
            }
        }

        if (more) {
            int q = p ^ 1;
            As[q][a_row][a_c4+0]      = wmma::__float_to_tf32(av0.x);
            As[q][a_row][a_c4+1]      = wmma::__float_to_tf32(av0.y);
            As[q][a_row][a_c4+2]      = wmma::__float_to_tf32(av0.z);
            As[q][a_row][a_c4+3]      = wmma::__float_to_tf32(av0.w);
            As[q][a_row+64][a_c4+0]   = wmma::__float_to_tf32(av1.x);
            As[q][a_row+64][a_c4+1]   = wmma::__float_to_tf32(av1.y);
            As[q][a_row+64][a_c4+2]   = wmma::__float_to_tf32(av1.z);
            As[q][a_row+64][a_c4+3]   = wmma::__float_to_tf32(av1.w);
            Bs[q][b_row][b_c4+0]      = wmma::__float_to_tf32(bv0.x);
            Bs[q][b_row][b_c4+1]      = wmma::__float_to_tf32(bv0.y);
            Bs[q][b_row][b_c4+2]      = wmma::__float_to_tf32(bv0.z);
            Bs[q][b_row][b_c4+3]      = wmma::__float_to_tf32(bv0.w);
            Bs[q][b_row][b_c4+64]     = wmma::__float_to_tf32(bv1.x);
            Bs[q][b_row][b_c4+65]     = wmma::__float_to_tf32(bv1.y);
            Bs[q][b_row][b_c4+66]     = wmma::__float_to_tf32(bv1.z);
            Bs[q][b_row][b_c4+67]     = wmma::__float_to_tf32(bv1.w);
        }
        __syncthreads();
        p ^= 1;
    }

    // ---- epilogue: per-warp 16x16 staging aliased onto As (free now) ----
    float* ws = &As[0][0][0] + wid * 16 * W_LD;
    const int h_head = (bn + cg * 64) >> 6;
    #pragma unroll
    for (int i = 0; i < 2; i++) {
        #pragma unroll
        for (int j = 0; j < 4; j++) {
            wmma::store_matrix_sync(ws, acc[i][j], W_LD, wmma::mem_row_major);
            __syncwarp();
            int row0 = bm + rt * 32 + i * 16;
            int col0 = bn + cg * 64 + j * 16;
            int r0 = lane >> 2;
            int c4 = (lane & 3) * 4;
            float4 bvv = *(const float4*)(bias + col0 + c4);
            #pragma unroll
            for (int rr = 0; rr < 2; rr++) {
                int r = r0 + rr * 8;
                float4 v = *(float4*)&ws[r * W_LD + c4];
                v.x += bvv.x; v.y += bvv.y; v.z += bvv.z; v.w += bvv.w;
                if (MODE == 1) {
                    v.x = fmaxf(v.x, 0.f); v.y = fmaxf(v.y, 0.f);
                    v.z = fmaxf(v.z, 0.f); v.w = fmaxf(v.w, 0.f);
                }
                int m = row0 + r;
                if (MODE == 2) {
                    int g = m >> 10, l = m & 1023;
                    int dd = j * 16 + c4;
                    float* dst = C + (((size_t)(g * HEADS + h_head)) * LSEQ + l) * DH + dd;
                    *(float4*)dst = v;
                } else {
                    *(float4*)(C + (size_t)m * N + col0 + c4) = v;
                }
            }
            __syncwarp();
        }
    }
}

// ---------------- attention: WMMA TF32 flash, 32 q x 64 k tiles --------------
#define AQ 32
#define AK 64
#define KV_LD 68
#define P_LD  72

__global__ void __launch_bounds__(256) attn_kernel(float* __restrict__ out_attn) {
    __shared__ float Qs [AQ][KV_LD];    // 8.7 KB  (tf32, pre-scaled)
    __shared__ float KVs[AK][KV_LD];    // 17.4 KB (K then V, tf32)
    __shared__ float Ps [AQ][P_LD];     // 9.2 KB  (S fp32, then P tf32)
    __shared__ float PVs[AQ][KV_LD];    // 8.7 KB

    const int tid = threadIdx.x;
    const int wid = tid >> 5;
    const int gh  = blockIdx.y;
    const int g   = gh >> 4, h = gh & 15;
    const int q0  = blockIdx.x * AQ;

    const float* Qg = g_q + (size_t)gh * LSEQ * DH;
    const float* Kg = g_k + (size_t)gh * LSEQ * DH;
    const float* Vg = g_v + (size_t)gh * LSEQ * DH;

    // load Q tile (scale folded, tf32): 512 float4, 2/thread
    #pragma unroll
    for (int t = 0; t < 2; t++) {
        int i = tid + t * 256;
        int r = i >> 4, c4 = (i & 15) * 4;
        float4 qv = *(const float4*)&Qg[(size_t)(q0 + r) * DH + c4];
        Qs[r][c4 + 0] = wmma::__float_to_tf32(qv.x * 0.125f);
        Qs[r][c4 + 1] = wmma::__float_to_tf32(qv.y * 0.125f);
        Qs[r][c4 + 2] = wmma::__float_to_tf32(qv.z * 0.125f);
        Qs[r][c4 + 3] = wmma::__float_to_tf32(qv.w * 0.125f);
    }
    __syncthreads();

    const int wr = (wid & 1) * 16;     // warp's q-row offset
    const int wc = (wid >> 1) * 16;    // warp's kc / dv offset

    const int q  = tid >> 3;
    const int c0 = tid & 7;

    float m_run = -1e30f, l_run = 0.f;
    float O[8];
    #pragma unroll
    for (int c = 0; c < 8; c++) O[c] = 0.f;

    for (int kt = 0; kt < LSEQ / AK; kt++) {
        // 1. K tile -> KVs (tf32). Prior PV mma reads finished (sync at end of iter).
        #pragma unroll
        for (int t = 0; t < 4; t++) {
            int i = tid + t * 256;
            int r = i >> 4, c4 = (i & 15) * 4;
            float4 kv = *(const float4*)&Kg[(size_t)(kt * AK + r) * DH + c4];
            KVs[r][c4 + 0] = wmma::__float_to_tf32(kv.x);
            KVs[r][c4 + 1] = wmma::__float_to_tf32(kv.y);
            KVs[r][c4 + 2] = wmma::__float_to_tf32(kv.z);
            KVs[r][c4 + 3] = wmma::__float_to_tf32(kv.w);
        }
        __syncthreads();

        // 2. S = Q . K^T : one 16x16 fragment per warp
        {
            wmma::fragment<wmma::accumulator, 16, 16, 8, float> sacc;
            wmma::fill_fragment(sacc, 0.0f);
            #pragma unroll
            for (int d0 = 0; d0 < DH; d0 += 8) {
                wmma::fragment<wmma::matrix_a, 16, 16, 8, wmma::precision::tf32, wmma::row_major> af;
                wmma::load_matrix_sync(af, &Qs[wr][d0], KV_LD);
                wmma::fragment<wmma::matrix_b, 16, 16, 8, wmma::precision::tf32, wmma::col_major> bf;
                wmma::load_matrix_sync(bf, &KVs[wc][d0], KV_LD);
                wmma::mma_sync(sacc, af, bf, sacc);
            }
            wmma::store_matrix_sync(&Ps[wr][wc], sacc, P_LD, wmma::mem_row_major);
        }
        __syncthreads();

        // 3. issue V loads, do online softmax, then store V (KVs free post-sync)
        float4 vv[4];
        #pragma unroll
        for (int t = 0; t < 4; t++) {
            int i = tid + t * 256;
            int r = i >> 4, c4 = (i & 15) * 4;
            vv[t] = *(const float4*)&Vg[(size_t)(kt * AK + r) * DH + c4];
        }

        float s[8];
        #pragma unroll
        for (int c = 0; c < 8; c++) s[c] = Ps[q][c0 + c * 8];
        float mloc = s[0];
        #pragma unroll
        for (int c = 1; c < 8; c++) mloc = fmaxf(mloc, s[c]);
        #pragma unroll
        for (int off = 4; off; off >>= 1)
            mloc = fmaxf(mloc, __shfl_xor_sync(0xffffffffu, mloc, off, 8));
        float m_new = fmaxf(m_run, mloc);
        float corr  = __expf(m_run - m_new);
        float psum = 0.f;
        #pragma unroll
        for (int c = 0; c < 8; c++) { s[c] = __expf(s[c] - m_new); psum += s[c]; }
        #pragma unroll
        for (int off = 4; off; off >>= 1)
            psum += __shfl_xor_sync(0xffffffffu, psum, off, 8);
        l_run = l_run * corr + psum;
        m_run = m_new;
        #pragma unroll
        for (int c = 0; c < 8; c++) {
            O[c] *= corr;
            Ps[q][c0 + c * 8] = wmma::__float_to_tf32(s[c]);
        }

        #pragma unroll
        for (int t = 0; t < 4; t++) {
            int i = tid + t * 256;
            int r = i >> 4, c4 = (i & 15) * 4;
            KVs[r][c4 + 0] = wmma::__float_to_tf32(vv[t].x);
            KVs[r][c4 + 1] = wmma::__float_to_tf32(vv[t].y);
            KVs[r][c4 + 2] = wmma::__float_to_tf32(vv[t].z);
            KVs[r][c4 + 3] = wmma::__float_to_tf32(vv[t].w);
        }
        __syncthreads();

        // 4. PV = P . V : one 16x16 fragment per warp
        {
            wmma::fragment<wmma::accumulator, 16, 16, 8, float> pacc;
            wmma::fill_fragment(pacc, 0.0f);
            #pragma unroll
            for (int k8 = 0; k8 < AK; k8 += 8) {
                wmma::fragment<wmma::matrix_a, 16, 16, 8, wmma::precision::tf32, wmma::row_major> af;
                wmma::load_matrix_sync(af, &Ps[wr][k8], P_LD);
                wmma::fragment<wmma::matrix_b, 16, 16, 8, wmma::precision::tf32, wmma::row_major> bf;
                wmma::load_matrix_sync(bf, &KVs[k8][wc], KV_LD);
                wmma::mma_sync(pacc, af, bf, pacc);
            }
            wmma::store_matrix_sync(&PVs[wr][wc], pacc, KV_LD, wmma::mem_row_major);
        }
        __syncthreads();

        // 5. accumulate
        #pragma unroll
        for (int c = 0; c < 8; c++) O[c] += PVs[q][c0 + c * 8];
    }

    float inv = 1.f / l_run;
    int b = g >> 1, j = g & 1;
    int srow = (q0 + q) * DIL + j;
    float* outp = out_attn + ((size_t)b * SEQ + srow) * D_MODEL + h * DH;
    #pragma unroll
    for (int c = 0; c < 8; c++) outp[c0 + c * 8] = O[c] * inv;
}

// ---------------- residual + layernorm ---------------------------------------
__global__ void __launch_bounds__(256) ln_kernel(
    const float* __restrict__ a, const float* __restrict__ r,
    const float* __restrict__ gamma, const float* __restrict__ beta,
    float* __restrict__ out)
{
    __shared__ float s_sum[8], s_sq[8];
    __shared__ float s_mu, s_rstd;
    const int row = blockIdx.x, tid = threadIdx.x;
    const size_t base = (size_t)row * D_MODEL;

    float4 av = ((const float4*)(a + base))[tid];
    float4 rv = ((const float4*)(r + base))[tid];
    float v0 = av.x + rv.x, v1 = av.y + rv.y, v2 = av.z + rv.z, v3 = av.w + rv.w;

    float sum = v0 + v1 + v2 + v3;
    float sq  = v0*v0 + v1*v1 + v2*v2 + v3*v3;
    #pragma unroll
    for (int off = 16; off; off >>= 1) {
        sum += __shfl_xor_sync(0xffffffffu, sum, off);
        sq  += __shfl_xor_sync(0xffffffffu, sq,  off);
    }
    if ((tid & 31) == 0) { s_sum[tid >> 5] = sum; s_sq[tid >> 5] = sq; }
    __syncthreads();
    if (tid == 0) {
        float ts = 0.f, tq = 0.f;
        #pragma unroll
        for (int i = 0; i < 8; i++) { ts += s_sum[i]; tq += s_sq[i]; }
        float mu  = ts * (1.f / D_MODEL);
        float var = tq * (1.f / D_MODEL) - mu * mu;
        s_mu = mu;
        s_rstd = rsqrtf(var + LN_EPS);
    }
    __syncthreads();
    float mu = s_mu, rstd = s_rstd;

    float4 gv = ((const float4*)gamma)[tid];
    float4 bv = ((const float4*)beta)[tid];
    float4 o;
    o.x = (v0 - mu) * rstd * gv.x + bv.x;
    o.y = (v1 - mu) * rstd * gv.y + bv.y;
    o.z = (v2 - mu) * rstd * gv.z + bv.z;
    o.w = (v3 - mu) * rstd * gv.w + bv.w;
    ((float4*)(out + base))[tid] = o;
}

// ---------------- launch ------------------------------------------------------
extern "C" void kernel_launch(void* const* d_in, const int* in_sizes, int n_in,
                              void* d_out, int out_size) {
    const float* x     = (const float*)d_in[0];
    const float* Wq    = (const float*)d_in[1];
    const float* bq    = (const float*)d_in[2];
    const float* Wk    = (const float*)d_in[3];
    const float* bk    = (const float*)d_in[4];
    const float* Wv    = (const float*)d_in[5];
    const float* bv    = (const float*)d_in[6];
    const float* Wo    = (const float*)d_in[7];
    const float* bo    = (const float*)d_in[8];
    const float* ln1_g = (const float*)d_in[9];
    const float* ln1_b = (const float*)d_in[10];
    const float* W1    = (const float*)d_in[11];
    const float* b1    = (const float*)d_in[12];
    const float* W2    = (const float*)d_in[13];
    const float* b2    = (const float*)d_in[14];
    const float* ln2_g = (const float*)d_in[15];
    const float* ln2_b = (const float*)d_in[16];
    float* out = (float*)d_out;

    float *p_xg, *p_q, *p_k, *p_v, *p_attn, *p_tmp1, *p_fin, *p_hid, *p_tmp2;
    cudaGetSymbolAddress((void**)&p_xg,   g_xg);
    cudaGetSymbolAddress((void**)&p_q,    g_q);
    cudaGetSymbolAddress((void**)&p_k,    g_k);
    cudaGetSymbolAddress((void**)&p_v,    g_v);
    cudaGetSymbolAddress((void**)&p_attn, g_attn);
    cudaGetSymbolAddress((void**)&p_tmp1, g_tmp1);
    cudaGetSymbolAddress((void**)&p_fin,  g_fin);
    cudaGetSymbolAddress((void**)&p_hid,  g_hid);
    cudaGetSymbolAddress((void**)&p_tmp2, g_tmp2);

    gather_kernel<<<MROWS, 256>>>(x);

    dim3 gD(D_MODEL / BN, MROWS / BM);        // (8, 64)
    wmma_gemm_kernel<2><<<gD, 256>>>(p_xg, Wq, bq, p_q, MROWS, D_MODEL, D_MODEL);
    wmma_gemm_kernel<2><<<gD, 256>>>(p_xg, Wk, bk, p_k, MROWS, D_MODEL, D_MODEL);
    wmma_gemm_kernel<2><<<gD, 256>>>(p_xg, Wv, bv, p_v, MROWS, D_MODEL, D_MODEL);

    dim3 gAtt(LSEQ / AQ, GRP * HEADS);        // (32, 128)
    attn_kernel<<<gAtt, 256>>>(p_attn);

    wmma_gemm_kernel<0><<<gD, 256>>>(p_attn, Wo, bo, p_tmp1, MROWS, D_MODEL, D_MODEL);

    ln_kernel<<<MROWS, 256>>>(p_tmp1, x, ln1_g, ln1_b, p_fin);

    dim3 gH(HIDDEN / BN, MROWS / BM);         // (32, 64)
    wmma_gemm_kernel<1><<<gH, 256>>>(p_fin, W1, b1, p_hid, MROWS, HIDDEN, D_MODEL);

    wmma_gemm_kernel<0><<<gD, 256>>>(p_hid, W2, b2, p_tmp2, MROWS, D_MODEL, HIDDEN);

    ln_kernel<<<MROWS, 256>>>(p_tmp2, p_fin, ln2_g, ln2_b, out);
}

// round 15
// speedup vs baseline: 1.6270x; 1.2367x over previous
#include <cuda_runtime.h>
#include <mma.h>
#include <cstdint>

using namespace nvcuda;

// ---------------- problem constants ----------------
#define D_MODEL 1024
#define HEADS   16
#define DH      64
#define HIDDEN  4096
#define BATCH   4
#define SEQ     2048
#define DIL     2
#define GRP     (BATCH*DIL)      // 8
#define LSEQ    (SEQ/DIL)        // 1024
#define MROWS   (BATCH*SEQ)      // 8192
#define LN_EPS  1e-5f

// ---------------- scratch ----------------------------------------------------
__device__ float g_xg  [MROWS * D_MODEL];
__device__ float g_q   [GRP * HEADS * LSEQ * DH];
__device__ float g_k   [GRP * HEADS * LSEQ * DH];
__device__ float g_v   [GRP * HEADS * LSEQ * DH];
__device__ float g_attn[MROWS * D_MODEL];
__device__ float g_tmp1[MROWS * D_MODEL];
__device__ float g_fin [MROWS * D_MODEL];
__device__ float g_hid [MROWS * HIDDEN];
__device__ float g_tmp2[MROWS * D_MODEL];

// ---------------- gather -----------------------------------------------------
__global__ void __launch_bounds__(256) gather_kernel(const float* __restrict__ x) {
    int m = blockIdx.x;
    int g = m >> 10, l = m & 1023;
    int b = g >> 1,  j = g & 1;
    int s = l * DIL + j;
    const float4* src = (const float4*)(x + ((size_t)b * SEQ + s) * D_MODEL);
    float4* dst = (float4*)(g_xg + (size_t)m * D_MODEL);
    dst[threadIdx.x] = src[threadIdx.x];
}

// ---------------- TF32 WMMA GEMM: 128x128, BK=16, single-buffer (R13) --------
#define BM 128
#define BN 128
#define BKK 16
#define A_LD 24      // 128 x 24 floats
#define B_LD 136     // 16 x 136 floats
#define W_LD 20      // per-warp epilogue staging 16 x 20

template<int MODE>
__global__ void __launch_bounds__(256) wmma_gemm_kernel(
    const float* __restrict__ A, const float* __restrict__ Bm,
    const float* __restrict__ bias, float* __restrict__ C,
    int M, int N, int K)
{
    __shared__ float As[BM][A_LD];        // 12.0 KB
    __shared__ float Bs[BKK][B_LD];       //  8.5 KB
    __shared__ float Ws[8][16][W_LD];     // 10.0 KB

    const int tid  = threadIdx.x;
    const int wid  = tid >> 5;
    const int lane = tid & 31;
    const int bm = blockIdx.y * BM;
    const int bn = blockIdx.x * BN;

    const int rt = wid & 3;      // warp row group: rows rt*32 .. rt*32+31
    const int cg = wid >> 2;     // warp col group: cols cg*64 .. cg*64+63

    const int a_row = tid >> 2;            // 0..63
    const int a_c4  = (tid & 3) * 4;       // 0,4,8,12
    const int b_row = tid >> 4;            // 0..15
    const int b_c4  = (tid & 15) * 4;      // 0..60

    const float* Aptr0 = A + (size_t)(bm + a_row) * K + a_c4;
    const float* Aptr1 = A + (size_t)(bm + a_row + 64) * K + a_c4;
    const float* Bptr0 = Bm + (size_t)b_row * N + bn + b_c4;
    const float* Bptr1 = Bm + (size_t)b_row * N + bn + b_c4 + 64;

    wmma::fragment<wmma::accumulator, 16, 16, 8, float> acc[2][4];
    #pragma unroll
    for (int i = 0; i < 2; i++)
        #pragma unroll
        for (int j = 0; j < 4; j++) wmma::fill_fragment(acc[i][j], 0.0f);

    // prefetch first tile
    float4 av0 = *(const float4*)(Aptr0);
    float4 av1 = *(const float4*)(Aptr1);
    float4 bv0 = *(const float4*)(Bptr0);
    float4 bv1 = *(const float4*)(Bptr1);

    for (int k0 = 0; k0 < K; k0 += BKK) {
        As[a_row][a_c4 + 0]      = wmma::__float_to_tf32(av0.x);
        As[a_row][a_c4 + 1]      = wmma::__float_to_tf32(av0.y);
        As[a_row][a_c4 + 2]      = wmma::__float_to_tf32(av0.z);
        As[a_row][a_c4 + 3]      = wmma::__float_to_tf32(av0.w);
        As[a_row + 64][a_c4 + 0] = wmma::__float_to_tf32(av1.x);
        As[a_row + 64][a_c4 + 1] = wmma::__float_to_tf32(av1.y);
        As[a_row + 64][a_c4 + 2] = wmma::__float_to_tf32(av1.z);
        As[a_row + 64][a_c4 + 3] = wmma::__float_to_tf32(av1.w);
        Bs[b_row][b_c4 + 0]      = wmma::__float_to_tf32(bv0.x);
        Bs[b_row][b_c4 + 1]      = wmma::__float_to_tf32(bv0.y);
        Bs[b_row][b_c4 + 2]      = wmma::__float_to_tf32(bv0.z);
        Bs[b_row][b_c4 + 3]      = wmma::__float_to_tf32(bv0.w);
        Bs[b_row][b_c4 + 64]     = wmma::__float_to_tf32(bv1.x);
        Bs[b_row][b_c4 + 65]     = wmma::__float_to_tf32(bv1.y);
        Bs[b_row][b_c4 + 66]     = wmma::__float_to_tf32(bv1.z);
        Bs[b_row][b_c4 + 67]     = wmma::__float_to_tf32(bv1.w);
        __syncthreads();

        int kn = k0 + BKK;
        if (kn < K) {
            av0 = *(const float4*)(Aptr0 + kn);
            av1 = *(const float4*)(Aptr1 + kn);
            bv0 = *(const float4*)(Bptr0 + (size_t)kn * N);
            bv1 = *(const float4*)(Bptr1 + (size_t)kn * N);
        }

        #pragma unroll
        for (int kk = 0; kk < BKK; kk += 8) {
            wmma::fragment<wmma::matrix_a, 16, 16, 8, wmma::precision::tf32, wmma::row_major> a_frag[2];
            wmma::load_matrix_sync(a_frag[0], &As[rt * 32][kk], A_LD);
            wmma::load_matrix_sync(a_frag[1], &As[rt * 32 + 16][kk], A_LD);
            #pragma unroll
            for (int j = 0; j < 4; j++) {
                wmma::fragment<wmma::matrix_b, 16, 16, 8, wmma::precision::tf32, wmma::row_major> b_frag;
                wmma::load_matrix_sync(b_frag, &Bs[kk][cg * 64 + j * 16], B_LD);
                wmma::mma_sync(acc[0][j], a_frag[0], b_frag, acc[0][j]);
                wmma::mma_sync(acc[1][j], a_frag[1], b_frag, acc[1][j]);
            }
        }
        __syncthreads();
    }

    // ---- per-warp epilogue ----
    const int h_head = (bn + cg * 64) >> 6;
    #pragma unroll
    for (int i = 0; i < 2; i++) {
        #pragma unroll
        for (int j = 0; j < 4; j++) {
            wmma::store_matrix_sync(&Ws[wid][0][0], acc[i][j], W_LD, wmma::mem_row_major);
            __syncwarp();
            int row0 = bm + rt * 32 + i * 16;
            int col0 = bn + cg * 64 + j * 16;
            int r0 = lane >> 2;
            int c4 = (lane & 3) * 4;
            float4 bvv = *(const float4*)(bias + col0 + c4);
            #pragma unroll
            for (int rr = 0; rr < 2; rr++) {
                int r = r0 + rr * 8;
                float4 v = *(float4*)&Ws[wid][r][c4];
                v.x += bvv.x; v.y += bvv.y; v.z += bvv.z; v.w += bvv.w;
                if (MODE == 1) {
                    v.x = fmaxf(v.x, 0.f); v.y = fmaxf(v.y, 0.f);
                    v.z = fmaxf(v.z, 0.f); v.w = fmaxf(v.w, 0.f);
                }
                int m = row0 + r;
                if (MODE == 2) {
                    int g = m >> 10, l = m & 1023;
                    int dd = j * 16 + c4;
                    float* dst = C + (((size_t)(g * HEADS + h_head)) * LSEQ + l) * DH + dd;
                    *(float4*)dst = v;
                } else {
                    *(float4*)(C + (size_t)m * N + col0 + c4) = v;
                }
            }
            __syncwarp();
        }
    }
}

// ---------------- attention: WMMA TF32 flash, 32 q x 64 k tiles (R14) --------
#define AQ 32
#define AK 64
#define KV_LD 68
#define P_LD  72

__global__ void __launch_bounds__(256) attn_kernel(float* __restrict__ out_attn) {
    __shared__ float Qs [AQ][KV_LD];
    __shared__ float KVs[AK][KV_LD];
    __shared__ float Ps [AQ][P_LD];
    __shared__ float PVs[AQ][KV_LD];

    const int tid = threadIdx.x;
    const int wid = tid >> 5;
    const int gh  = blockIdx.y;
    const int g   = gh >> 4, h = gh & 15;
    const int q0  = blockIdx.x * AQ;

    const float* Qg = g_q + (size_t)gh * LSEQ * DH;
    const float* Kg = g_k + (size_t)gh * LSEQ * DH;
    const float* Vg = g_v + (size_t)gh * LSEQ * DH;

    #pragma unroll
    for (int t = 0; t < 2; t++) {
        int i = tid + t * 256;
        int r = i >> 4, c4 = (i & 15) * 4;
        float4 qv = *(const float4*)&Qg[(size_t)(q0 + r) * DH + c4];
        Qs[r][c4 + 0] = wmma::__float_to_tf32(qv.x * 0.125f);
        Qs[r][c4 + 1] = wmma::__float_to_tf32(qv.y * 0.125f);
        Qs[r][c4 + 2] = wmma::__float_to_tf32(qv.z * 0.125f);
        Qs[r][c4 + 3] = wmma::__float_to_tf32(qv.w * 0.125f);
    }
    __syncthreads();

    const int wr = (wid & 1) * 16;
    const int wc = (wid >> 1) * 16;

    const int q  = tid >> 3;
    const int c0 = tid & 7;

    float m_run = -1e30f, l_run = 0.f;
    float O[8];
    #pragma unroll
    for (int c = 0; c < 8; c++) O[c] = 0.f;

    for (int kt = 0; kt < LSEQ / AK; kt++) {
        #pragma unroll
        for (int t = 0; t < 4; t++) {
            int i = tid + t * 256;
            int r = i >> 4, c4 = (i & 15) * 4;
            float4 kv = *(const float4*)&Kg[(size_t)(kt * AK + r) * DH + c4];
            KVs[r][c4 + 0] = wmma::__float_to_tf32(kv.x);
            KVs[r][c4 + 1] = wmma::__float_to_tf32(kv.y);
            KVs[r][c4 + 2] = wmma::__float_to_tf32(kv.z);
            KVs[r][c4 + 3] = wmma::__float_to_tf32(kv.w);
        }
        __syncthreads();

        {
            wmma::fragment<wmma::accumulator, 16, 16, 8, float> sacc;
            wmma::fill_fragment(sacc, 0.0f);
            #pragma unroll
            for (int d0 = 0; d0 < DH; d0 += 8) {
                wmma::fragment<wmma::matrix_a, 16, 16, 8, wmma::precision::tf32, wmma::row_major> af;
                wmma::load_matrix_sync(af, &Qs[wr][d0], KV_LD);
                wmma::fragment<wmma::matrix_b, 16, 16, 8, wmma::precision::tf32, wmma::col_major> bf;
                wmma::load_matrix_sync(bf, &KVs[wc][d0], KV_LD);
                wmma::mma_sync(sacc, af, bf, sacc);
            }
            wmma::store_matrix_sync(&Ps[wr][wc], sacc, P_LD, wmma::mem_row_major);
        }
        __syncthreads();

        float4 vv[4];
        #pragma unroll
        for (int t = 0; t < 4; t++) {
            int i = tid + t * 256;
            int r = i >> 4, c4 = (i & 15) * 4;
            vv[t] = *(const float4*)&Vg[(size_t)(kt * AK + r) * DH + c4];
        }

        float s[8];
        #pragma unroll
        for (int c = 0; c < 8; c++) s[c] = Ps[q][c0 + c * 8];
        float mloc = s[0];
        #pragma unroll
        for (int c = 1; c < 8; c++) mloc = fmaxf(mloc, s[c]);
        #pragma unroll
        for (int off = 4; off; off >>= 1)
            mloc = fmaxf(mloc, __shfl_xor_sync(0xffffffffu, mloc, off, 8));
        float m_new = fmaxf(m_run, mloc);
        float corr  = __expf(m_run - m_new);
        float psum = 0.f;
        #pragma unroll
        for (int c = 0; c < 8; c++) { s[c] = __expf(s[c] - m_new); psum += s[c]; }
        #pragma unroll
        for (int off = 4; off; off >>= 1)
            psum += __shfl_xor_sync(0xffffffffu, psum, off, 8);
        l_run = l_run * corr + psum;
        m_run = m_new;
        #pragma unroll
        for (int c = 0; c < 8; c++) {
            O[c] *= corr;
            Ps[q][c0 + c * 8] = wmma::__float_to_tf32(s[c]);
        }

        #pragma unroll
        for (int t = 0; t < 4; t++) {
            int i = tid + t * 256;
            int r = i >> 4, c4 = (i & 15) * 4;
            KVs[r][c4 + 0] = wmma::__float_to_tf32(vv[t].x);
            KVs[r][c4 + 1] = wmma::__float_to_tf32(vv[t].y);
            KVs[r][c4 + 2] = wmma::__float_to_tf32(vv[t].z);
            KVs[r][c4 + 3] = wmma::__float_to_tf32(vv[t].w);
        }
        __syncthreads();

        {
            wmma::fragment<wmma::accumulator, 16, 16, 8, float> pacc;
            wmma::fill_fragment(pacc, 0.0f);
            #pragma unroll
            for (int k8 = 0; k8 < AK; k8 += 8) {
                wmma::fragment<wmma::matrix_a, 16, 16, 8, wmma::precision::tf32, wmma::row_major> af;
                wmma::load_matrix_sync(af, &Ps[wr][k8], P_LD);
                wmma::fragment<wmma::matrix_b, 16, 16, 8, wmma::precision::tf32, wmma::row_major> bf;
                wmma::load_matrix_sync(bf, &KVs[k8][wc], KV_LD);
                wmma::mma_sync(pacc, af, bf, pacc);
            }
            wmma::store_matrix_sync(&PVs[wr][wc], pacc, KV_LD, wmma::mem_row_major);
        }
        __syncthreads();

        #pragma unroll
        for (int c = 0; c < 8; c++) O[c] += PVs[q][c0 + c * 8];
    }

    float inv = 1.f / l_run;
    int b = g >> 1, j = g & 1;
    int srow = (q0 + q) * DIL + j;
    float* outp = out_attn + ((size_t)b * SEQ + srow) * D_MODEL + h * DH;
    #pragma unroll
    for (int c = 0; c < 8; c++) outp[c0 + c * 8] = O[c] * inv;
}

// ---------------- residual + layernorm ---------------------------------------
__global__ void __launch_bounds__(256) ln_kernel(
    const float* __restrict__ a, const float* __restrict__ r,
    const float* __restrict__ gamma, const float* __restrict__ beta,
    float* __restrict__ out)
{
    __shared__ float s_sum[8], s_sq[8];
    __shared__ float s_mu, s_rstd;
    const int row = blockIdx.x, tid = threadIdx.x;
    const size_t base = (size_t)row * D_MODEL;

    float4 av = ((const float4*)(a + base))[tid];
    float4 rv = ((const float4*)(r + base))[tid];
    float v0 = av.x + rv.x, v1 = av.y + rv.y, v2 = av.z + rv.z, v3 = av.w + rv.w;

    float sum = v0 + v1 + v2 + v3;
    float sq  = v0*v0 + v1*v1 + v2*v2 + v3*v3;
    #pragma unroll
    for (int off = 16; off; off >>= 1) {
        sum += __shfl_xor_sync(0xffffffffu, sum, off);
        sq  += __shfl_xor_sync(0xffffffffu, sq,  off);
    }
    if ((tid & 31) == 0) { s_sum[tid >> 5] = sum; s_sq[tid >> 5] = sq; }
    __syncthreads();
    if (tid == 0) {
        float ts = 0.f, tq = 0.f;
        #pragma unroll
        for (int i = 0; i < 8; i++) { ts += s_sum[i]; tq += s_sq[i]; }
        float mu  = ts * (1.f / D_MODEL);
        float var = tq * (1.f / D_MODEL) - mu * mu;
        s_mu = mu;
        s_rstd = rsqrtf(var + LN_EPS);
    }
    __syncthreads();
    float mu = s_mu, rstd = s_rstd;

    float4 gv = ((const float4*)gamma)[tid];
    float4 bv = ((const float4*)beta)[tid];
    float4 o;
    o.x = (v0 - mu) * rstd * gv.x + bv.x;
    o.y = (v1 - mu) * rstd * gv.y + bv.y;
    o.z = (v2 - mu) * rstd * gv.z + bv.z;
    o.w = (v3 - mu) * rstd * gv.w + bv.w;
    ((float4*)(out + base))[tid] = o;
}

// ---------------- launch ------------------------------------------------------
extern "C" void kernel_launch(void* const* d_in, const int* in_sizes, int n_in,
                              void* d_out, int out_size) {
    const float* x     = (const float*)d_in[0];
    const float* Wq    = (const float*)d_in[1];
    const float* bq    = (const float*)d_in[2];
    const float* Wk    = (const float*)d_in[3];
    const float* bk    = (const float*)d_in[4];
    const float* Wv    = (const float*)d_in[5];
    const float* bv    = (const float*)d_in[6];
    const float* Wo    = (const float*)d_in[7];
    const float* bo    = (const float*)d_in[8];
    const float* ln1_g = (const float*)d_in[9];
    const float* ln1_b = (const float*)d_in[10];
    const float* W1    = (const float*)d_in[11];
    const float* b1    = (const float*)d_in[12];
    const float* W2    = (const float*)d_in[13];
    const float* b2    = (const float*)d_in[14];
    const float* ln2_g = (const float*)d_in[15];
    const float* ln2_b = (const float*)d_in[16];
    float* out = (float*)d_out;

    float *p_xg, *p_q, *p_k, *p_v, *p_attn, *p_tmp1, *p_fin, *p_hid, *p_tmp2;
    cudaGetSymbolAddress((void**)&p_xg,   g_xg);
    cudaGetSymbolAddress((void**)&p_q,    g_q);
    cudaGetSymbolAddress((void**)&p_k,    g_k);
    cudaGetSymbolAddress((void**)&p_v,    g_v);
    cudaGetSymbolAddress((void**)&p_attn, g_attn);
    cudaGetSymbolAddress((void**)&p_tmp1, g_tmp1);
    cudaGetSymbolAddress((void**)&p_fin,  g_fin);
    cudaGetSymbolAddress((void**)&p_hid,  g_hid);
    cudaGetSymbolAddress((void**)&p_tmp2, g_tmp2);

    gather_kernel<<<MROWS, 256>>>(x);

    dim3 gD(D_MODEL / BN, MROWS / BM);        // (8, 64)
    wmma_gemm_kernel<2><<<gD, 256>>>(p_xg, Wq, bq, p_q, MROWS, D_MODEL, D_MODEL);
    wmma_gemm_kernel<2><<<gD, 256>>>(p_xg, Wk, bk, p_k, MROWS, D_MODEL, D_MODEL);
    wmma_gemm_kernel<2><<<gD, 256>>>(p_xg, Wv, bv, p_v, MROWS, D_MODEL, D_MODEL);

    dim3 gAtt(LSEQ / AQ, GRP * HEADS);        // (32, 128)
    attn_kernel<<<gAtt, 256>>>(p_attn);

    wmma_gemm_kernel<0><<<gD, 256>>>(p_attn, Wo, bo, p_tmp1, MROWS, D_MODEL, D_MODEL);

    ln_kernel<<<MROWS, 256>>>(p_tmp1, x, ln1_g, ln1_b, p_fin);

    dim3 gH(HIDDEN / BN, MROWS / BM);         // (32, 64)
    wmma_gemm_kernel<1><<<gH, 256>>>(p_fin, W1, b1, p_hid, MROWS, HIDDEN, D_MODEL);

    wmma_gemm_kernel<0><<<gD, 256>>>(p_hid, W2, b2, p_tmp2, MROWS, D_MODEL, HIDDEN);

    ln_kernel<<<MROWS, 256>>>(p_tmp2, p_fin, ln2_g, ln2_b, out);
}